// round 12
// baseline (speedup 1.0000x reference)
#include <cuda_runtime.h>
#include <cstdint>
#include <math.h>

#define F_DIM 2048
#define K_DIM 128
#define BM    128
#define BK    32
#define NT    (F_DIM / BK)        // 64 k-tiles
#define STAGES 4

// ---- smem: raw row-major staged tiles, padded strides ----
#define ASTR_F   36               // A row stride (floats); bank = lane -> conflict-free frags
#define A_STAGE_B (BM * ASTR_F * 4)        // 18432
#define BSTR_F   136              // B row stride (floats); bank = 8*c0+l4 -> conflict-free
#define B_STAGE_B (BK * BSTR_F * 4)        // 17408
#define STAGE_B  (A_STAGE_B + B_STAGE_B)   // 35840
#define SM_GWS   (STAGES * STAGE_B)        // 143360 ; float2[2048] = 16384
#define SM_PS    (SM_GWS + 16384)          // float[128][4] = 2048
#define SM_RLIN  (SM_PS + 2048)
#define SM_RT    (SM_RLIN + 512)
#define SMEM_BYTES (SM_RT + 512)           // 162816

__device__ float  g_wcvt[F_DIM * K_DIM];   // tf32-rounded W, [f][n]
__device__ float2 g_ws[F_DIM];             // {wlin[f], exact sum_k W[f,k]^2}

__device__ __forceinline__ float to_tf32(float x) {
    uint32_t u;
    asm("cvt.rna.tf32.f32 %0, %1;" : "=r"(u) : "f"(x));
    return __uint_as_float(u);
}
__device__ __forceinline__ void mma_tf32(float* d, float a0, float a1,
                                         float a2, float a3, float b0, float b1) {
    asm volatile(
        "mma.sync.aligned.m16n8k8.row.col.f32.tf32.tf32.f32 "
        "{%0,%1,%2,%3}, {%4,%5,%6,%7}, {%8,%9}, {%0,%1,%2,%3};"
        : "+f"(d[0]), "+f"(d[1]), "+f"(d[2]), "+f"(d[3])
        : "r"(__float_as_uint(a0)), "r"(__float_as_uint(a1)),
          "r"(__float_as_uint(a2)), "r"(__float_as_uint(a3)),
          "r"(__float_as_uint(b0)), "r"(__float_as_uint(b1)));
}
__device__ __forceinline__ uint32_t smem_u32(const void* p) {
    uint32_t a;
    asm("{ .reg .u64 t; cvta.to.shared.u64 t, %1; cvt.u32.u64 %0, t; }" : "=r"(a) : "l"(p));
    return a;
}
__device__ __forceinline__ void cp16(uint32_t dst, const float* src) {
    asm volatile("cp.async.cg.shared.global [%0], [%1], 16;" :: "r"(dst), "l"(src));
}
#define CP_COMMIT() asm volatile("cp.async.commit_group;" ::: "memory")
#define CP_WAIT2()  asm volatile("cp.async.wait_group 2;" ::: "memory")

// ---------------- fused prologue ----------------
__global__ void prep_kernel(const float* __restrict__ kern,
                            const float* __restrict__ wlin) {
    const int gw = (blockIdx.x * blockDim.x + threadIdx.x) >> 5;  // 0..511
    const int lane = threadIdx.x & 31;
#pragma unroll
    for (int rr = 0; rr < 4; ++rr) {
        const int f = gw * 4 + rr;
        float4 v = *reinterpret_cast<const float4*>(kern + (size_t)f * K_DIM + lane * 4);
        float s = v.x * v.x + v.y * v.y + v.z * v.z + v.w * v.w;
#pragma unroll
        for (int off = 16; off >= 1; off >>= 1)
            s += __shfl_xor_sync(0xffffffffu, s, off);
        float4 c = make_float4(to_tf32(v.x), to_tf32(v.y), to_tf32(v.z), to_tf32(v.w));
        *reinterpret_cast<float4*>(g_wcvt + (size_t)f * K_DIM + lane * 4) = c;
        if (lane == 0) g_ws[f] = make_float2(wlin[f], s);
    }
}

// ---------------- main kernel: 512 threads, cp.async 4-stage ----------------
__global__ __launch_bounds__(512, 1) void fm_mma_kernel(
    const float* __restrict__ X, const float* __restrict__ blin,
    float* __restrict__ out) {
    extern __shared__ char smem[];
    const uint32_t sb = smem_u32(smem);
    float* gws  = reinterpret_cast<float*>(smem + SM_GWS);
    float* pS   = reinterpret_cast<float*>(smem + SM_PS);
    float* rowLin = reinterpret_cast<float*>(smem + SM_RLIN);
    float* rowT   = reinterpret_cast<float*>(smem + SM_RT);

    const int tid  = threadIdx.x;
    const int lane = tid & 31;
    const int wid  = tid >> 5;
    const int wm   = wid >> 2;              // 0..3 (32-row slice)
    const int wn   = wid & 3;               // 0..3 (32-col slice)
    const int l4   = lane >> 2;
    const int c0   = lane & 3;
    const int blockRow = blockIdx.x * BM;

    // cp.async mapping
    const bool isA = (tid < 256);
    const int arow = (tid & 255) >> 1;      // 0..127
    const int ah   = tid & 1;               // 16-float half
    const int brow = (tid & 255) >> 3;      // 0..31 (k-row)
    const int bseg = tid & 7;               // 16-float segment
    const float* aSrc = X + (size_t)(blockRow + arow) * F_DIM + ah * 16;
    const uint32_t aDst = sb + arow * (ASTR_F * 4) + ah * 64;
    const uint32_t bDst = sb + A_STAGE_B + brow * (BSTR_F * 4) + bseg * 64;

    // lin/t mapping: thread owns row lr, 8-float slice q
    const int lr = tid >> 2;
    const int q  = tid & 3;

    float linP = 0.f, tP = 0.f;
    float acc[2][4][4];
#pragma unroll
    for (int i = 0; i < 2; ++i)
#pragma unroll
        for (int j = 0; j < 4; ++j)
#pragma unroll
            for (int e = 0; e < 4; ++e) acc[i][j][e] = 0.f;

    auto issue = [&](int t) {
        const uint32_t so = (uint32_t)(t & (STAGES - 1)) * STAGE_B;
        if (isA) {
            const float* s = aSrc + t * BK;
            const uint32_t d = aDst + so;
            cp16(d, s); cp16(d + 16, s + 4); cp16(d + 32, s + 8); cp16(d + 48, s + 12);
        } else {
            const float* s = g_wcvt + (size_t)(t * BK + brow) * K_DIM + bseg * 16;
            const uint32_t d = bDst + so;
            cp16(d, s); cp16(d + 16, s + 4); cp16(d + 32, s + 8); cp16(d + 48, s + 12);
        }
    };

    // stage g_ws into smem
    {
        float4* dst = reinterpret_cast<float4*>(gws);
        const float4* src = reinterpret_cast<const float4*>(g_ws);
        dst[tid] = src[tid];
        dst[tid + 512] = src[tid + 512];
    }
    issue(0); CP_COMMIT();
    issue(1); CP_COMMIT();
    issue(2); CP_COMMIT();

    for (int t = 0; t < NT; ++t) {
        CP_WAIT2();
        __syncthreads();
        if (t + 3 < NT) issue(t + 3);
        CP_COMMIT();

        const char* stg = smem + (t & (STAGES - 1)) * STAGE_B;
        const float* As = reinterpret_cast<const float*>(stg);
        const float* Bs = reinterpret_cast<const float*>(stg + A_STAGE_B);

        // ---- MMA ----
        const int r0 = wm * 32 + l4;
#pragma unroll
        for (int ks = 0; ks < 4; ++ks) {
            float a[2][4];
#pragma unroll
            for (int i = 0; i < 2; ++i) {
                const int base = (r0 + i * 16) * ASTR_F + ks * 8 + c0;
                a[i][0] = As[base];
                a[i][1] = As[base + 8 * ASTR_F];
                a[i][2] = As[base + 4];
                a[i][3] = As[base + 8 * ASTR_F + 4];
            }
            const int bbase = (ks * 8 + c0) * BSTR_F + wn * 32 + l4;
#pragma unroll
            for (int j = 0; j < 4; ++j) {
                float b0 = Bs[bbase + j * 8];
                float b1 = Bs[bbase + 4 * BSTR_F + j * 8];
                mma_tf32(acc[0][j], a[0][0], a[0][1], a[0][2], a[0][3], b0, b1);
                mma_tf32(acc[1][j], a[1][0], a[1][1], a[1][2], a[1][3], b0, b1);
            }
        }

        // ---- fused lin/t from raw X in smem (exact fp32) ----
        {
            const float4* xa = reinterpret_cast<const float4*>(
                stg + lr * (ASTR_F * 4) + q * 32);
            float4 x0 = xa[0], x1 = xa[1];
            const float4* g = reinterpret_cast<const float4*>(gws) + t * 16 + q * 4;
            float4 g0 = g[0], g1 = g[1], g2 = g[2], g3 = g[3];
            linP += x0.x * g0.x + x0.y * g0.z + x0.z * g1.x + x0.w * g1.z
                  + x1.x * g2.x + x1.y * g2.z + x1.z * g3.x + x1.w * g3.z;
            tP   += x0.x * x0.x * g0.y + x0.y * x0.y * g0.w
                  + x0.z * x0.z * g1.y + x0.w * x0.w * g1.w
                  + x1.x * x1.x * g2.y + x1.y * x1.y * g2.w
                  + x1.z * x1.z * g3.y + x1.w * x1.w * g3.w;
        }
        __syncthreads();
    }

    // ---- per-row lin/t reduce (4 q-lanes per row, adjacent lanes) ----
    linP += __shfl_xor_sync(0xffffffffu, linP, 1);
    linP += __shfl_xor_sync(0xffffffffu, linP, 2);
    tP   += __shfl_xor_sync(0xffffffffu, tP, 1);
    tP   += __shfl_xor_sync(0xffffffffu, tP, 2);
    if (q == 0) { rowLin[lr] = linP; rowT[lr] = tP; }

    // ---- epilogue: per-warp sum of squares over its 32 cols ----
#pragma unroll
    for (int i = 0; i < 2; ++i) {
        float sLo = 0.f, sHi = 0.f;
#pragma unroll
        for (int j = 0; j < 4; ++j) {
            sLo += acc[i][j][0] * acc[i][j][0] + acc[i][j][1] * acc[i][j][1];
            sHi += acc[i][j][2] * acc[i][j][2] + acc[i][j][3] * acc[i][j][3];
        }
        sLo += __shfl_xor_sync(0xffffffffu, sLo, 1);
        sLo += __shfl_xor_sync(0xffffffffu, sLo, 2);
        sHi += __shfl_xor_sync(0xffffffffu, sHi, 1);
        sHi += __shfl_xor_sync(0xffffffffu, sHi, 2);
        if (c0 == 0) {
            int rowL = wm * 32 + i * 16 + l4;
            pS[rowL * 4 + wn] = sLo;
            pS[(rowL + 8) * 4 + wn] = sHi;
        }
    }
    __syncthreads();

    if (tid < BM) {
        float ssum = pS[tid * 4] + pS[tid * 4 + 1] + pS[tid * 4 + 2] + pS[tid * 4 + 3];
        float cross = 0.5f * (ssum - rowT[tid]) * (1.0f / (float)K_DIM);
        float z = rowLin[tid] + blin[0] + cross;
        out[blockRow + tid] = 1.0f / (1.0f + expf(-z));
    }
}

extern "C" void kernel_launch(void* const* d_in, const int* in_sizes, int n_in,
                              void* d_out, int out_size) {
    const float* x    = (const float*)d_in[0];
    const float* kern = (const float*)d_in[1];
    const float* wlin = (const float*)d_in[2];
    const float* blin = (const float*)d_in[3];
    float* out = (float*)d_out;
    const int B = out_size;

    cudaFuncSetAttribute(fm_mma_kernel,
                         cudaFuncAttributeMaxDynamicSharedMemorySize, SMEM_BYTES);
    prep_kernel<<<64, 256>>>(kern, wlin);
    fm_mma_kernel<<<B / BM, 512, SMEM_BYTES>>>(x, blin, out);
}

// round 13
// speedup vs baseline: 1.1297x; 1.1297x over previous
#include <cuda_runtime.h>
#include <cstdint>
#include <math.h>

#define F_DIM 2048
#define K_DIM 128
#define BM    128
#define BK    32
#define NT    (F_DIM / BK)     // 64 k-tiles

// ---- smem layout (proven conflict-free, identical to R8) ----
#define A_BLK_F4   33
#define A_BUF_F4   (32 * A_BLK_F4)
#define B_BLK_F2   132
#define B_BUF_F2   (16 * B_BLK_F2)
#define SM_A_BYTES (2 * A_BUF_F4 * 16)        // 33792
#define SM_B_OFF   SM_A_BYTES
#define SM_B_BYTES (2 * B_BUF_F2 * 8)         // 33792
#define SM_PS_OFF  (SM_B_OFF + SM_B_BYTES)    // float[128][4]
#define SM_RLIN_OFF (SM_PS_OFF + 2048)
#define SM_RT_OFF   (SM_RLIN_OFF + 512)
#define SMEM_BYTES  (SM_RT_OFF + 512)         // 71680

__device__ float  g_wcvt[F_DIM * K_DIM];   // tf32-rounded W, [f][n]
__device__ float2 g_ws[F_DIM];             // {wlin[f], exact sum_k W[f,k]^2}

__device__ __forceinline__ float to_tf32(float x) {
    uint32_t u;
    asm("cvt.rna.tf32.f32 %0, %1;" : "=r"(u) : "f"(x));
    return __uint_as_float(u);
}
__device__ __forceinline__ void mma_tf32(float* d, uint32_t a0, uint32_t a1,
                                         uint32_t a2, uint32_t a3,
                                         uint32_t b0, uint32_t b1) {
    asm volatile(
        "mma.sync.aligned.m16n8k8.row.col.f32.tf32.tf32.f32 "
        "{%0,%1,%2,%3}, {%4,%5,%6,%7}, {%8,%9}, {%0,%1,%2,%3};"
        : "+f"(d[0]), "+f"(d[1]), "+f"(d[2]), "+f"(d[3])
        : "r"(a0), "r"(a1), "r"(a2), "r"(a3), "r"(b0), "r"(b1));
}

// ---------------- fused prologue ----------------
__global__ void prep_kernel(const float* __restrict__ kern,
                            const float* __restrict__ wlin) {
    const int gw = (blockIdx.x * blockDim.x + threadIdx.x) >> 5;  // 0..511
    const int lane = threadIdx.x & 31;
#pragma unroll
    for (int rr = 0; rr < 4; ++rr) {
        const int f = gw * 4 + rr;
        float4 v = *reinterpret_cast<const float4*>(kern + (size_t)f * K_DIM + lane * 4);
        float s = v.x * v.x + v.y * v.y + v.z * v.z + v.w * v.w;
#pragma unroll
        for (int off = 16; off >= 1; off >>= 1)
            s += __shfl_xor_sync(0xffffffffu, s, off);
        float4 c = make_float4(to_tf32(v.x), to_tf32(v.y), to_tf32(v.z), to_tf32(v.w));
        *reinterpret_cast<float4*>(g_wcvt + (size_t)f * K_DIM + lane * 4) = c;
        if (lane == 0) g_ws[f] = make_float2(wlin[f], s);
    }
}

// ---------------- main kernel: 512 threads, 16 warps ----------------
__global__ __launch_bounds__(512, 1) void fm_mma_kernel(
    const float* __restrict__ X, const float* __restrict__ blin,
    float* __restrict__ out) {
    extern __shared__ char smem[];
    float4* Af  = reinterpret_cast<float4*>(smem);
    float2* Bf  = reinterpret_cast<float2*>(smem + SM_B_OFF);
    float*  pS  = reinterpret_cast<float*>(smem + SM_PS_OFF);
    float*  rowLin = reinterpret_cast<float*>(smem + SM_RLIN_OFF);
    float*  rowT   = reinterpret_cast<float*>(smem + SM_RT_OFF);

    const int tid  = threadIdx.x;
    const int lane = tid & 31;
    const int wid  = tid >> 5;
    const int wm   = wid >> 2;              // 0..3 (32-row slice)
    const int wn   = wid & 3;               // 0..3 (32-col slice)
    const int blockRow = blockIdx.x * BM;
    const bool isA = (tid < 256);

    // A loader mapping (tid 0..255)
    const int rid  = tid >> 2;
    const int cseg = tid & 3;
    const int rlow = (rid & 7) | ((rid >> 3) << 4);
    const int wm2i = rid >> 3;
    // B loader mapping (tid 256..511)
    const int t2    = tid & 255;
    const int ksl   = t2 >> 6;
    const int nseg2 = (t2 >> 2) & 15;
    const int c0l   = t2 & 3;

    const float* xLo = X + (size_t)(blockRow + rlow) * F_DIM + cseg * 8;
    const float* xHi = xLo + 8 * F_DIM;
    const float* wLo = g_wcvt + (size_t)(ksl * 8 + c0l) * K_DIM + nseg2 * 8;
    const float* wHi = wLo + 4 * K_DIM;
    const float4* wsP = reinterpret_cast<const float4*>(g_ws) + cseg * 4;

    float linLo = 0.f, linHi = 0.f, tLo = 0.f, tHi = 0.f;
    float acc[2][4][4];
#pragma unroll
    for (int i = 0; i < 2; ++i)
#pragma unroll
        for (int j = 0; j < 4; ++j)
#pragma unroll
            for (int e = 0; e < 4; ++e) acc[i][j][e] = 0.f;

    float4 st[4];   // contiguous staged tile

    auto ldg_tile = [&](int f0) {
        if (isA) {
            st[0] = *reinterpret_cast<const float4*>(xLo + f0);
            st[1] = *reinterpret_cast<const float4*>(xLo + f0 + 4);
            st[2] = *reinterpret_cast<const float4*>(xHi + f0);
            st[3] = *reinterpret_cast<const float4*>(xHi + f0 + 4);
            const float4* wp = wsP + f0 / 2;
            const float* lo = reinterpret_cast<const float*>(&st[0]);
            const float* hi = reinterpret_cast<const float*>(&st[2]);
#pragma unroll
            for (int u = 0; u < 4; ++u) {
                float4 g = __ldg(wp + u);
                float a0 = lo[2 * u], a1 = lo[2 * u + 1];
                float b0 = hi[2 * u], b1 = hi[2 * u + 1];
                linLo += a0 * g.x + a1 * g.z;  tLo += a0 * a0 * g.y + a1 * a1 * g.w;
                linHi += b0 * g.x + b1 * g.z;  tHi += b0 * b0 * g.y + b1 * b1 * g.w;
            }
        } else {
            st[0] = *reinterpret_cast<const float4*>(wLo + (size_t)f0 * K_DIM);
            st[1] = *reinterpret_cast<const float4*>(wLo + (size_t)f0 * K_DIM + 4);
            st[2] = *reinterpret_cast<const float4*>(wHi + (size_t)f0 * K_DIM);
            st[3] = *reinterpret_cast<const float4*>(wHi + (size_t)f0 * K_DIM + 4);
        }
    };
    auto sts_tile = [&](int buf) {
        if (isA) {
            float4* ad = Af + buf * A_BUF_F4 + (wm2i * 4 + cseg) * A_BLK_F4;
            const float* lo = reinterpret_cast<const float*>(&st[0]);
            const float* hi = reinterpret_cast<const float*>(&st[2]);
#pragma unroll
            for (int e = 0; e < 4; ++e) {
                int fl = (rlow & 7) * 4 + e;
                ad[fl] = make_float4(lo[e], hi[e], lo[e + 4], hi[e + 4]);
            }
        } else {
            float4* bd = reinterpret_cast<float4*>(Bf + buf * B_BUF_F2) +
                         (ksl * 4 + c0l) * (B_BLK_F2 / 2) + nseg2 * 4;
            const float* bl = reinterpret_cast<const float*>(&st[0]);
            const float* bh = reinterpret_cast<const float*>(&st[2]);
#pragma unroll
            for (int e = 0; e < 4; ++e)
                bd[e] = make_float4(bl[2 * e], bh[2 * e], bl[2 * e + 1], bh[2 * e + 1]);
        }
    };

    ldg_tile(0);
    sts_tile(0);
    __syncthreads();

    for (int t = 0; t < NT; ++t) {
        const int nt = t + 1;
        if (nt < NT) ldg_tile(nt * BK);

        // ---- compute tile t from buffer t&1, ks-level software pipeline ----
        {
            const float4* ab = Af + (t & 1) * A_BUF_F4 + (wm * 2) * 4 * A_BLK_F4 + lane;
            const float2* bb = Bf + (t & 1) * B_BUF_F2 +
                               (lane & 3) * B_BLK_F2 + wn * 32 + (lane >> 2);

            float4 a0[2], a1[2];
            float2 bfr[2][4];
            // preload ks=0 fragments
            a0[0] = ab[0];
            a1[0] = ab[4 * A_BLK_F4];
#pragma unroll
            for (int j = 0; j < 4; ++j) bfr[0][j] = bb[j * 8];

#pragma unroll
            for (int ks = 0; ks < 4; ++ks) {
                const int cur = ks & 1;
                const int nxt = cur ^ 1;
                if (ks < 3) {   // fetch ks+1 frags; interleaves with HMMA below
                    a0[nxt] = ab[(ks + 1) * A_BLK_F4];
                    a1[nxt] = ab[(4 + ks + 1) * A_BLK_F4];
                    const float2* bk = bb + (ks + 1) * 4 * B_BLK_F2;
#pragma unroll
                    for (int j = 0; j < 4; ++j) bfr[nxt][j] = bk[j * 8];
                }
#pragma unroll
                for (int j = 0; j < 4; ++j) {
                    float2 b = bfr[cur][j];
                    mma_tf32(acc[0][j],
                             __float_as_uint(a0[cur].x), __float_as_uint(a0[cur].y),
                             __float_as_uint(a0[cur].z), __float_as_uint(a0[cur].w),
                             __float_as_uint(b.x), __float_as_uint(b.y));
                    mma_tf32(acc[1][j],
                             __float_as_uint(a1[cur].x), __float_as_uint(a1[cur].y),
                             __float_as_uint(a1[cur].z), __float_as_uint(a1[cur].w),
                             __float_as_uint(b.x), __float_as_uint(b.y));
                }
            }
        }

        if (nt < NT) sts_tile(nt & 1);
        __syncthreads();
    }

    // ---- per-row lin/t reduce (A loaders only) ----
    if (isA) {
        linLo += __shfl_xor_sync(0xffffffffu, linLo, 1);
        linLo += __shfl_xor_sync(0xffffffffu, linLo, 2);
        linHi += __shfl_xor_sync(0xffffffffu, linHi, 1);
        linHi += __shfl_xor_sync(0xffffffffu, linHi, 2);
        tLo += __shfl_xor_sync(0xffffffffu, tLo, 1);
        tLo += __shfl_xor_sync(0xffffffffu, tLo, 2);
        tHi += __shfl_xor_sync(0xffffffffu, tHi, 1);
        tHi += __shfl_xor_sync(0xffffffffu, tHi, 2);
        if (cseg == 0) {
            rowLin[rlow] = linLo;  rowT[rlow] = tLo;
            rowLin[rlow + 8] = linHi;  rowT[rlow + 8] = tHi;
        }
    }

    // ---- epilogue: per-warp sum of squares over its 32 cols ----
#pragma unroll
    for (int i = 0; i < 2; ++i) {
        float sLo = 0.f, sHi = 0.f;
#pragma unroll
        for (int j = 0; j < 4; ++j) {
            sLo += acc[i][j][0] * acc[i][j][0] + acc[i][j][1] * acc[i][j][1];
            sHi += acc[i][j][2] * acc[i][j][2] + acc[i][j][3] * acc[i][j][3];
        }
        sLo += __shfl_xor_sync(0xffffffffu, sLo, 1);
        sLo += __shfl_xor_sync(0xffffffffu, sLo, 2);
        sHi += __shfl_xor_sync(0xffffffffu, sHi, 1);
        sHi += __shfl_xor_sync(0xffffffffu, sHi, 2);
        if ((lane & 3) == 0) {
            int rowL = wm * 32 + i * 16 + (lane >> 2);
            pS[rowL * 4 + wn] = sLo;
            pS[(rowL + 8) * 4 + wn] = sHi;
        }
    }
    __syncthreads();

    if (tid < BM) {
        float ssum = pS[tid * 4] + pS[tid * 4 + 1] + pS[tid * 4 + 2] + pS[tid * 4 + 3];
        float cross = 0.5f * (ssum - rowT[tid]) * (1.0f / (float)K_DIM);
        float z = rowLin[tid] + blin[0] + cross;
        out[blockRow + tid] = 1.0f / (1.0f + expf(-z));
    }
}

extern "C" void kernel_launch(void* const* d_in, const int* in_sizes, int n_in,
                              void* d_out, int out_size) {
    const float* x    = (const float*)d_in[0];
    const float* kern = (const float*)d_in[1];
    const float* wlin = (const float*)d_in[2];
    const float* blin = (const float*)d_in[3];
    float* out = (float*)d_out;
    const int B = out_size;

    cudaFuncSetAttribute(fm_mma_kernel,
                         cudaFuncAttributeMaxDynamicSharedMemorySize, SMEM_BYTES);
    prep_kernel<<<64, 256>>>(kern, wlin);
    fm_mma_kernel<<<B / BM, 512, SMEM_BYTES>>>(x, blin, out);
}

// round 14
// speedup vs baseline: 1.4875x; 1.3167x over previous
#include <cuda_runtime.h>
#include <cuda_fp16.h>
#include <cstdint>
#include <math.h>

#define F_DIM 2048
#define K_DIM 128
#define BM    128
#define BK    32
#define NT    (F_DIM / BK)     // 64 k-tiles

// ---- smem layout (bytes) ----
// A: frag blocks, 16 per buffer (g 0..7 x ks 0..1), 512B + 16 pad = 528B each
#define A_BUF_B   (16 * 528)              // 8448
#define SM_B      (2 * A_BUF_B)           // 16896
// B: 16 pair-rows per tile, stride 136 uint32 (544B) -> conflict-free consumer
#define B_STR_U   136
#define B_BUF_U   (16 * B_STR_U)          // 2176 uint32 = 8704 B
#define SM_PS     (SM_B + 2 * B_BUF_U * 4)    // 34304
#define SM_RLIN   (SM_PS + 2048)
#define SM_RT     (SM_RLIN + 512)
#define SMEM_TOTAL (SM_RT + 512)          // 37376 < 48K -> static

__device__ uint32_t g_wpk[(F_DIM / 2) * K_DIM];  // fp16-pair-packed W: [p][n], pair along f
__device__ float2   g_ws[F_DIM];                 // {wlin[f], exact sum_k W[f,k]^2}

__device__ __forceinline__ uint32_t pack2h(float a, float b) {
    __half2 h = __floats2half2_rn(a, b);
    return *reinterpret_cast<uint32_t*>(&h);
}
__device__ __forceinline__ void mma_f16(float* d, uint32_t a0, uint32_t a1,
                                        uint32_t a2, uint32_t a3,
                                        uint32_t b0, uint32_t b1) {
    asm volatile(
        "mma.sync.aligned.m16n8k16.row.col.f32.f16.f16.f32 "
        "{%0,%1,%2,%3}, {%4,%5,%6,%7}, {%8,%9}, {%0,%1,%2,%3};"
        : "+f"(d[0]), "+f"(d[1]), "+f"(d[2]), "+f"(d[3])
        : "r"(a0), "r"(a1), "r"(a2), "r"(a3), "r"(b0), "r"(b1));
}

// ---------------- fused prologue: s_f, wlin, fp16 pair-pack of W ----------------
__global__ void prep_kernel(const float* __restrict__ kern,
                            const float* __restrict__ wlin) {
    const int gw = (blockIdx.x * blockDim.x + threadIdx.x) >> 5;  // 0..511
    const int lane = threadIdx.x & 31;
    float4 prev = make_float4(0.f, 0.f, 0.f, 0.f);
#pragma unroll
    for (int rr = 0; rr < 4; ++rr) {
        const int f = gw * 4 + rr;
        float4 v = *reinterpret_cast<const float4*>(kern + (size_t)f * K_DIM + lane * 4);
        float s = v.x * v.x + v.y * v.y + v.z * v.z + v.w * v.w;
#pragma unroll
        for (int off = 16; off >= 1; off >>= 1)
            s += __shfl_xor_sync(0xffffffffu, s, off);
        if (lane == 0) g_ws[f] = make_float2(wlin[f], s);
        if ((rr & 1) == 0) {
            prev = v;
        } else {
            uint4 pk;
            pk.x = pack2h(prev.x, v.x);
            pk.y = pack2h(prev.y, v.y);
            pk.z = pack2h(prev.z, v.z);
            pk.w = pack2h(prev.w, v.w);
            *reinterpret_cast<uint4*>(
                g_wpk + (size_t)(gw * 2 + (rr >> 1)) * K_DIM + lane * 4) = pk;
        }
    }
}

// ---------------- main kernel: 512 threads, fp16 m16n8k16 ----------------
__global__ __launch_bounds__(512, 1) void fm_mma_kernel(
    const float* __restrict__ X, const float* __restrict__ blin,
    float* __restrict__ out) {
    __shared__ __align__(16) char smem[SMEM_TOTAL];
    float* pS     = reinterpret_cast<float*>(smem + SM_PS);
    float* rowLin = reinterpret_cast<float*>(smem + SM_RLIN);
    float* rowT   = reinterpret_cast<float*>(smem + SM_RT);

    const int tid  = threadIdx.x;
    const int lane = tid & 31;
    const int wid  = tid >> 5;
    const int wm   = wid >> 2;              // 0..3 (32-row slice)
    const int wn   = wid & 3;               // 0..3 (32-col slice)
    const int l4   = lane >> 2;
    const int c0   = lane & 3;
    const int blockRow = blockIdx.x * BM;
    const bool isA = (tid < 256);

    // A loader mapping (tid 0..255): rows (rlow, rlow+8), 8-k segment cseg
    const int rid  = tid >> 2;              // 0..63
    const int cseg = tid & 3;               // 0..3
    const int rlow = (rid & 7) | ((rid >> 3) << 4);
    const int gA   = rid >> 3;              // 16-row group 0..7
    const int rloc = rid & 7;
    // B loader mapping (tid 256..511): pair-row p, 8-n segment n16
    const int t2   = tid & 255;
    const int pB   = t2 >> 4;               // 0..15
    const int n16  = t2 & 15;               // 0..15

    const float* xLo = X + (size_t)(blockRow + rlow) * F_DIM + cseg * 8;
    const float* xHi = xLo + 8 * F_DIM;
    const float4* wsP = reinterpret_cast<const float4*>(g_ws) + cseg * 4;

    float linLo = 0.f, linHi = 0.f, tLo = 0.f, tHi = 0.f;
    float acc[2][4][4];
#pragma unroll
    for (int i = 0; i < 2; ++i)
#pragma unroll
        for (int j = 0; j < 4; ++j)
#pragma unroll
            for (int e = 0; e < 4; ++e) acc[i][j][e] = 0.f;

    float4 st[4];   // staged tile (A: 16 floats; B: 2x uint4 punned)

    auto ldg_tile = [&](int t) {
        if (isA) {
            const int f0 = t * BK;
            st[0] = *reinterpret_cast<const float4*>(xLo + f0);
            st[1] = *reinterpret_cast<const float4*>(xLo + f0 + 4);
            st[2] = *reinterpret_cast<const float4*>(xHi + f0);
            st[3] = *reinterpret_cast<const float4*>(xHi + f0 + 4);
            const float4* wp = wsP + f0 / 2;
            const float* lo = reinterpret_cast<const float*>(&st[0]);
            const float* hi = reinterpret_cast<const float*>(&st[2]);
#pragma unroll
            for (int u = 0; u < 4; ++u) {
                float4 g = __ldg(wp + u);
                float a0 = lo[2 * u], a1 = lo[2 * u + 1];
                float b0 = hi[2 * u], b1 = hi[2 * u + 1];
                linLo += a0 * g.x + a1 * g.z;  tLo += a0 * a0 * g.y + a1 * a1 * g.w;
                linHi += b0 * g.x + b1 * g.z;  tHi += b0 * b0 * g.y + b1 * b1 * g.w;
            }
        } else {
            const uint32_t* src = g_wpk + (size_t)(t * 16 + pB) * K_DIM + n16 * 8;
            *reinterpret_cast<uint4*>(&st[0]) = *reinterpret_cast<const uint4*>(src);
            *reinterpret_cast<uint4*>(&st[1]) = *reinterpret_cast<const uint4*>(src + 4);
        }
    };
    auto sts_tile = [&](int buf) {
        if (isA) {
            char* ad = smem + buf * A_BUF_B + (gA * 2 + (cseg >> 1)) * 528;
            const float* lo = reinterpret_cast<const float*>(&st[0]);
            const float* hi = reinterpret_cast<const float*>(&st[2]);
            const int hs = cseg & 1;
#pragma unroll
            for (int c = 0; c < 4; ++c) {
                uint2 v;
                v.x = pack2h(lo[2 * c], lo[2 * c + 1]);
                v.y = pack2h(hi[2 * c], hi[2 * c + 1]);
                *reinterpret_cast<uint2*>(ad + (4 * rloc + c) * 16 + hs * 8) = v;
            }
        } else {
            uint32_t* bd = reinterpret_cast<uint32_t*>(smem + SM_B) +
                           buf * B_BUF_U + pB * B_STR_U + n16 * 8;
            *reinterpret_cast<uint4*>(bd) = *reinterpret_cast<const uint4*>(&st[0]);
            *reinterpret_cast<uint4*>(bd + 4) = *reinterpret_cast<const uint4*>(&st[1]);
        }
    };

    ldg_tile(0);
    sts_tile(0);
    __syncthreads();

    for (int t = 0; t < NT; ++t) {
        const int nt = t + 1;
        if (nt < NT) ldg_tile(nt);

        // ---- compute tile t from buffer t&1 ----
        {
            const char* ab = smem + (t & 1) * A_BUF_B;
            const uint32_t* bs = reinterpret_cast<const uint32_t*>(smem + SM_B) +
                                 (t & 1) * B_BUF_U + c0 * B_STR_U + wn * 32 + l4;
#pragma unroll
            for (int ks = 0; ks < 2; ++ks) {
                uint4 a0 = *reinterpret_cast<const uint4*>(
                    ab + ((wm * 2 + 0) * 2 + ks) * 528 + lane * 16);
                uint4 a1 = *reinterpret_cast<const uint4*>(
                    ab + ((wm * 2 + 1) * 2 + ks) * 528 + lane * 16);
                const uint32_t* bk = bs + ks * 8 * B_STR_U;
#pragma unroll
                for (int j = 0; j < 4; ++j) {
                    uint32_t b0 = bk[8 * j];
                    uint32_t b1 = bk[4 * B_STR_U + 8 * j];
                    mma_f16(acc[0][j], a0.x, a0.y, a0.z, a0.w, b0, b1);
                    mma_f16(acc[1][j], a1.x, a1.y, a1.z, a1.w, b0, b1);
                }
            }
        }

        if (nt < NT) sts_tile(nt & 1);
        __syncthreads();
    }

    // ---- per-row lin/t reduce (A loaders only; 4 cseg lanes per row pair) ----
    if (isA) {
        linLo += __shfl_xor_sync(0xffffffffu, linLo, 1);
        linLo += __shfl_xor_sync(0xffffffffu, linLo, 2);
        linHi += __shfl_xor_sync(0xffffffffu, linHi, 1);
        linHi += __shfl_xor_sync(0xffffffffu, linHi, 2);
        tLo += __shfl_xor_sync(0xffffffffu, tLo, 1);
        tLo += __shfl_xor_sync(0xffffffffu, tLo, 2);
        tHi += __shfl_xor_sync(0xffffffffu, tHi, 1);
        tHi += __shfl_xor_sync(0xffffffffu, tHi, 2);
        if (cseg == 0) {
            rowLin[rlow] = linLo;  rowT[rlow] = tLo;
            rowLin[rlow + 8] = linHi;  rowT[rlow + 8] = tHi;
        }
    }

    // ---- epilogue: per-warp sum of squares over its 32 cols ----
#pragma unroll
    for (int i = 0; i < 2; ++i) {
        float sLo = 0.f, sHi = 0.f;
#pragma unroll
        for (int j = 0; j < 4; ++j) {
            sLo += acc[i][j][0] * acc[i][j][0] + acc[i][j][1] * acc[i][j][1];
            sHi += acc[i][j][2] * acc[i][j][2] + acc[i][j][3] * acc[i][j][3];
        }
        sLo += __shfl_xor_sync(0xffffffffu, sLo, 1);
        sLo += __shfl_xor_sync(0xffffffffu, sLo, 2);
        sHi += __shfl_xor_sync(0xffffffffu, sHi, 1);
        sHi += __shfl_xor_sync(0xffffffffu, sHi, 2);
        if (c0 == 0) {
            int rowL = wm * 32 + i * 16 + l4;
            pS[rowL * 4 + wn] = sLo;
            pS[(rowL + 8) * 4 + wn] = sHi;
        }
    }
    __syncthreads();

    if (tid < BM) {
        float ssum = pS[tid * 4] + pS[tid * 4 + 1] + pS[tid * 4 + 2] + pS[tid * 4 + 3];
        float cross = 0.5f * (ssum - rowT[tid]) * (1.0f / (float)K_DIM);
        float z = rowLin[tid] + blin[0] + cross;
        out[blockRow + tid] = 1.0f / (1.0f + expf(-z));
    }
}

extern "C" void kernel_launch(void* const* d_in, const int* in_sizes, int n_in,
                              void* d_out, int out_size) {
    const float* x    = (const float*)d_in[0];
    const float* kern = (const float*)d_in[1];
    const float* wlin = (const float*)d_in[2];
    const float* blin = (const float*)d_in[3];
    float* out = (float*)d_out;
    const int B = out_size;

    prep_kernel<<<64, 256>>>(kern, wlin);
    fm_mma_kernel<<<B / BM, 512>>>(x, blin, out);
}